// round 10
// baseline (speedup 1.0000x reference)
#include <cuda_runtime.h>
#include <cstddef>

#define Bn 128
#define Sn 512
#define Dn 256
#define Hn 512
#define On 256
#define NCTA 128

// ---------------------------------------------------------------------------
// Device scratch (static __device__ globals — the sanctioned no-alloc scratch)
// ---------------------------------------------------------------------------
__device__ __align__(16) float g_wx[(size_t)Bn * Sn * 4 * Hn];   // [b*S+s][4H]
__device__ __align__(16) float g_state[2 * Hn * Bn * 2];         // ping-pong, float2(h,c), k-major
__device__ unsigned g_count = 0;
__device__ unsigned g_sense = 0;

// ---------------------------------------------------------------------------
// SGEMM with bias: C[M,N] = A[M,K] @ B[K,N] + bias[N]   (unchanged, passing)
// ---------------------------------------------------------------------------
__global__ void __launch_bounds__(256)
sgemm_bias(const float* __restrict__ A, const float* __restrict__ Bm,
           const float* __restrict__ bias, float* __restrict__ C,
           int M, int N, int K)
{
    if (C == nullptr) C = g_wx;

    __shared__ float As[16][132];
    __shared__ float Bs[16][132];

    const int tid = threadIdx.x;
    const int tx = tid & 15;
    const int ty = tid >> 4;
    const int m0 = blockIdx.y * 128;
    const int n0 = blockIdx.x * 128;

    float acc[8][8];
#pragma unroll
    for (int i = 0; i < 8; i++)
#pragma unroll
        for (int j = 0; j < 8; j++) acc[i][j] = 0.0f;

    const int ar = tid >> 1;
    const int ah = tid & 1;
    const float* Abase = A + (size_t)(m0 + ar) * K + ah * 8;
    const int bk = tid >> 5;
    const int bc = (tid & 31) * 4;

    for (int k0 = 0; k0 < K; k0 += 16) {
        float4 a0 = *reinterpret_cast<const float4*>(Abase + k0);
        float4 a1 = *reinterpret_cast<const float4*>(Abase + k0 + 4);
        As[ah * 8 + 0][ar] = a0.x; As[ah * 8 + 1][ar] = a0.y;
        As[ah * 8 + 2][ar] = a0.z; As[ah * 8 + 3][ar] = a0.w;
        As[ah * 8 + 4][ar] = a1.x; As[ah * 8 + 5][ar] = a1.y;
        As[ah * 8 + 6][ar] = a1.z; As[ah * 8 + 7][ar] = a1.w;
#pragma unroll
        for (int p = 0; p < 16; p += 8) {
            float4 bv = *reinterpret_cast<const float4*>(
                Bm + (size_t)(k0 + bk + p) * N + n0 + bc);
            *reinterpret_cast<float4*>(&Bs[bk + p][bc]) = bv;
        }
        __syncthreads();

#pragma unroll
        for (int k = 0; k < 16; k++) {
            float ra[8], rb[8];
            *reinterpret_cast<float4*>(ra)     = *reinterpret_cast<const float4*>(&As[k][ty * 8]);
            *reinterpret_cast<float4*>(ra + 4) = *reinterpret_cast<const float4*>(&As[k][ty * 8 + 4]);
            *reinterpret_cast<float4*>(rb)     = *reinterpret_cast<const float4*>(&Bs[k][tx * 8]);
            *reinterpret_cast<float4*>(rb + 4) = *reinterpret_cast<const float4*>(&Bs[k][tx * 8 + 4]);
#pragma unroll
            for (int i = 0; i < 8; i++)
#pragma unroll
                for (int j = 0; j < 8; j++)
                    acc[i][j] = fmaf(ra[i], rb[j], acc[i][j]);
        }
        __syncthreads();
    }

    float bb[8];
#pragma unroll
    for (int j = 0; j < 8; j++) bb[j] = bias[n0 + tx * 8 + j];

#pragma unroll
    for (int i = 0; i < 8; i++) {
        const size_t row = (size_t)(m0 + ty * 8 + i) * N + n0 + tx * 8;
        float4 o0, o1;
        o0.x = acc[i][0] + bb[0]; o0.y = acc[i][1] + bb[1];
        o0.z = acc[i][2] + bb[2]; o0.w = acc[i][3] + bb[3];
        o1.x = acc[i][4] + bb[4]; o1.y = acc[i][5] + bb[5];
        o1.z = acc[i][6] + bb[6]; o1.w = acc[i][7] + bb[7];
        *reinterpret_cast<float4*>(&C[row])     = o0;
        *reinterpret_cast<float4*>(&C[row + 4]) = o1;
    }
}

// ---------------------------------------------------------------------------
// f32x2 packed helpers (sm_103a)
// ---------------------------------------------------------------------------
__device__ __forceinline__ unsigned long long pack2(float v) {
    unsigned long long r;
    asm("mov.b64 %0, {%1, %1};" : "=l"(r) : "f"(v));
    return r;
}
__device__ __forceinline__ void fma2(unsigned long long& d,
                                     unsigned long long a, unsigned long long b) {
    asm("fma.rn.f32x2 %0, %1, %2, %0;" : "+l"(d) : "l"(a), "l"(b));
}
__device__ __forceinline__ float2 unpack2(unsigned long long v) {
    float2 r;
    asm("mov.b64 {%0, %1}, %2;" : "=f"(r.x), "=f"(r.y) : "l"(v));
    return r;
}

__device__ __forceinline__ float sigf(float x) { return 1.0f / (1.0f + __expf(-x)); }

__device__ __forceinline__ void grid_barrier(unsigned& lsense)
{
    __threadfence();
    __syncthreads();
    if (threadIdx.x == 0) {
        const unsigned target = lsense ^ 1u;
        if (atomicAdd(&g_count, 1u) == (unsigned)(NCTA - 1)) {
            g_count = 0;
            __threadfence();
            *((volatile unsigned*)&g_sense) = target;
        } else {
            while (*((volatile unsigned*)&g_sense) != target) { }
        }
    }
    __syncthreads();
    lsense ^= 1u;
}

// ---------------------------------------------------------------------------
// Persistent recurrence: 128 CTAs x 256 threads.
// CTA cid owns hidden columns j = cid*4 .. cid*4+3.
// Thread = (b = tid&127, kg = tid>>7) computes all 4 j over its K-half with
// f32x2-packed FMAs. State loads are chunked + double-buffered (MLP=16) so
// the ~300-cycle L2 latency is fully covered by each chunk's 160 FFMA2s.
// ---------------------------------------------------------------------------

// Load one 16-k chunk of state (float2 h,c per k) into a register buffer.
#define LOAD_CHUNK(BUF, CH) do {                                          \
    const int kn_ = kb0 + (CH) * 16;                                      \
    _Pragma("unroll")                                                     \
    for (int i_ = 0; i_ < 16; i_++)                                       \
        BUF[i_] = __ldcg(st + (size_t)(kn_ + i_) * 128 + b);              \
} while (0)

// Consume one 16-k chunk: 8 k-pairs x 20 fma2.
#define COMPUTE_CHUNK(BUF, CH) do {                                       \
    _Pragma("unroll")                                                     \
    for (int t_ = 0; t_ < 8; t_++) {                                      \
        const int kp_ = kp0 + (CH) * 8 + t_;                              \
        const unsigned long long hh0 = pack2(BUF[2 * t_].x);              \
        const unsigned long long cc0 = pack2(BUF[2 * t_].y);              \
        const unsigned long long hh1 = pack2(BUF[2 * t_ + 1].x);          \
        const unsigned long long cc1 = pack2(BUF[2 * t_ + 1].y);          \
        _Pragma("unroll")                                                 \
        for (int g_ = 0; g_ < 4; g_++) {                                  \
            _Pragma("unroll")                                             \
            for (int p_ = 0; p_ < 2; p_++) {                              \
                ulonglong2 w = *reinterpret_cast<const ulonglong2*>(      \
                    Us2 + (size_t)(((g_ * 2 + p_) * 256 + kp_) * 2));     \
                fma2(acc[g_ * 2 + p_], hh0, w.x);                         \
                fma2(acc[g_ * 2 + p_], hh1, w.y);                         \
            }                                                             \
        }                                                                 \
        _Pragma("unroll")                                                 \
        for (int p_ = 0; p_ < 2; p_++) {                                  \
            ulonglong2 w = *reinterpret_cast<const ulonglong2*>(          \
                Wd2 + (size_t)((p_ * 256 + kp_) * 2));                    \
            fma2(acc[8 + p_], cc0, w.x);                                  \
            fma2(acc[8 + p_], cc1, w.y);                                  \
        }                                                                 \
    }                                                                     \
} while (0)

__global__ void __launch_bounds__(256, 1)
tlstm_recur(const float* __restrict__ U_all, const float* __restrict__ b_u,
            const float* __restrict__ W_d,  const float* __restrict__ b_d,
            const float* __restrict__ td,
            float* __restrict__ hs_out, float* __restrict__ cs_out)
{
    extern __shared__ unsigned long long smem_u[];
    unsigned long long* Us2 = smem_u;          // [ (g*2+p)*256 + kp ] x {k-even,k-odd} : 4096 ull
    unsigned long long* Wd2 = smem_u + 4096;   // [ p*256 + kp ] x {k-even,k-odd}       : 1024 ull
    float* red  = (float*)(smem_u + 5120);     // [b][20] partials : 2560 floats
    float* bu_s = red + 2560;                  // [g*4 + j] : 16
    float* bd_s = bu_s + 16;                   // [j] : 4

    const int tid = threadIdx.x;
    const int cid = blockIdx.x;
    const int b   = tid & 127;
    const int kg  = tid >> 7;          // which K-half

    // ---- one-time staging: packed weight pairs into SMEM ----
    {
        float* UsF = (float*)Us2;
        for (int i = tid; i < 8192; i += 256) {
            const int jj = i & 1;
            const int h  = (i >> 1) & 1;
            const int kp = (i >> 2) & 255;
            const int p  = (i >> 10) & 1;
            const int g  = i >> 11;
            const int k  = kp * 2 + h;
            UsF[i] = U_all[(size_t)k * 2048 + g * 512 + cid * 4 + p * 2 + jj];
        }
        float* WdF = (float*)Wd2;
        for (int i = tid; i < 2048; i += 256) {
            const int jj = i & 1;
            const int h  = (i >> 1) & 1;
            const int kp = (i >> 2) & 255;
            const int p  = i >> 10;
            const int k  = kp * 2 + h;
            WdF[i] = W_d[(size_t)k * 512 + cid * 4 + p * 2 + jj];
        }
        if (tid < 16) bu_s[tid] = b_u[(tid >> 2) * 512 + cid * 4 + (tid & 3)];
        if (tid < 4)  bd_s[tid] = b_d[cid * 4 + tid];
    }

    // zero ping buffer 0 (disjoint slice per CTA)
    {
        float2* stz = reinterpret_cast<float2*>(g_state);
        for (int i = tid; i < 512; i += 256)
            stz[cid * 512 + i] = make_float2(0.f, 0.f);
    }

    unsigned lsense = *((volatile unsigned*)&g_sense);
    grid_barrier(lsense);

    const int kp0 = kg * 128;          // first k-pair of this thread's half
    const int kb0 = kp0 * 2;           // first k

    for (int s = 0; s < Sn; s++) {
        if (s) grid_barrier(lsense);

        const float2* st = reinterpret_cast<const float2*>(g_state) + (size_t)(s & 1) * (Hn * Bn);
        float2*      stn = reinterpret_cast<float2*>(g_state) + (size_t)((s & 1) ^ 1) * (Hn * Bn);

        // ---- prefetch step operands (consumed after the dot loop) ----
        const float* wxb = g_wx + ((size_t)b * Sn + s) * 2048 + cid * 4;
        float wxa[4][4];
#pragma unroll
        for (int g = 0; g < 4; g++) {
            float4 v = __ldg(reinterpret_cast<const float4*>(wxb + g * 512));
            wxa[g][0] = v.x; wxa[g][1] = v.y; wxa[g][2] = v.z; wxa[g][3] = v.w;
        }
        float c_old[4];
#pragma unroll
        for (int j = 0; j < 4; j++)
            c_old[j] = __ldcg(st + (size_t)(cid * 4 + j) * 128 + b).y;
        const float tdv = __ldg(td + (size_t)b * Sn + s);

        // ---- dot products over this thread's K-half (chunked, MLP=16) ----
        unsigned long long acc[10];
#pragma unroll
        for (int i = 0; i < 10; i++) acc[i] = 0ull;

        float2 bufA[16], bufB[16];
        LOAD_CHUNK(bufA, 0);

#pragma unroll 1
        for (int ch = 0; ch < 16; ch += 2) {
            LOAD_CHUNK(bufB, ch + 1);
            COMPUTE_CHUNK(bufA, ch);
            if (ch + 2 < 16) LOAD_CHUNK(bufA, ch + 2);
            COMPUTE_CHUNK(bufB, ch + 1);
        }

        // ---- reduce the two K-halves via SMEM ----
        if (kg == 1) {
#pragma unroll
            for (int i = 0; i < 10; i++) {
                float2 r = unpack2(acc[i]);
                red[b * 20 + i * 2]     = r.x;
                red[b * 20 + i * 2 + 1] = r.y;
            }
        }
        __syncthreads();

        if (kg == 0) {
            float G[5][4];
#pragma unroll
            for (int i = 0; i < 10; i++) {
                float2 mine = unpack2(acc[i]);
                const int g = i >> 1;
                const int p = i & 1;
                G[g][p * 2 + 0] = mine.x + red[b * 20 + i * 2];
                G[g][p * 2 + 1] = mine.y + red[b * 20 + i * 2 + 1];
            }

            float hv[4], cv[4];
#pragma unroll
            for (int j = 0; j < 4; j++) {
                const float cst  = sigf(G[4][j] + bd_s[j]);
                const float cadj = c_old[j] - cst + cst * tdv;
                const float ff   = sigf(wxa[0][j] + G[0][j] + bu_s[j]);
                const float ii   = sigf(wxa[1][j] + G[1][j] + bu_s[4 + j]);
                const float oo   = sigf(wxa[2][j] + G[2][j] + bu_s[8 + j]);
                const float gg   = tanhf(wxa[3][j] + G[3][j] + bu_s[12 + j]);
                const float cn   = ff * cadj + ii * gg;
                const float hn   = oo * tanhf(cn);
                cv[j] = cn; hv[j] = hn;
                stn[(size_t)(cid * 4 + j) * 128 + b] = make_float2(hn, cn);
            }

            const size_t ob = ((size_t)b * Sn + s) * Hn + cid * 4;
            *reinterpret_cast<float4*>(hs_out + ob) = make_float4(hv[0], hv[1], hv[2], hv[3]);
            *reinterpret_cast<float4*>(cs_out + ob) = make_float4(cv[0], cv[1], cv[2], cv[3]);
        }
    }
}

// ---------------------------------------------------------------------------
// Launch
// ---------------------------------------------------------------------------
extern "C" void kernel_launch(void* const* d_in, const int* in_sizes, int n_in,
                              void* d_out, int out_size)
{
    const float* inputs     = (const float*)d_in[0];
    const float* time_diffs = (const float*)d_in[1];
    // d_in[2] = seq_lens (unused by reference)
    const float* W_all      = (const float*)d_in[3];
    const float* b_all      = (const float*)d_in[4];
    const float* U_all      = (const float*)d_in[5];
    const float* b_u        = (const float*)d_in[6];
    const float* W_d        = (const float*)d_in[7];
    const float* b_d        = (const float*)d_in[8];
    const float* W_out      = (const float*)d_in[9];
    const float* b_out      = (const float*)d_in[10];

    float* out = (float*)d_out;                        // [B,S,O]
    float* hs  = out + (size_t)Bn * Sn * On;           // [B,S,H]
    float* cs  = hs  + (size_t)Bn * Sn * Hn;           // [B,S,H]

    const int M = Bn * Sn;  // 65536

    // GEMM1: Wx = inputs @ W_all + b_all  -> g_wx
    {
        dim3 grid((4 * Hn) / 128, M / 128);
        sgemm_bias<<<grid, 256>>>(inputs, W_all, b_all, nullptr, M, 4 * Hn, Dn);
    }

    // Recurrence: persistent grid, grid-wide barrier per step
    {
        const int shmem = 5120 * 8 + 2560 * 4 + 20 * 4;  // 51280 B
        cudaFuncSetAttribute(tlstm_recur,
                             cudaFuncAttributeMaxDynamicSharedMemorySize, shmem);
        tlstm_recur<<<NCTA, 256, shmem>>>(U_all, b_u, W_d, b_d, time_diffs, hs, cs);
    }

    // GEMM2: outputs = hs @ W_out + b_out
    {
        dim3 grid(On / 128, M / 128);
        sgemm_bias<<<grid, 256>>>(hs, W_out, b_out, out, M, On, Hn);
    }
}

// round 11
// speedup vs baseline: 1.0050x; 1.0050x over previous
#include <cuda_runtime.h>
#include <cstddef>

#define Bn 128
#define Sn 512
#define Dn 256
#define Hn 512
#define On 256
#define NCTA 128

// ---------------------------------------------------------------------------
// Device scratch (static __device__ globals — the sanctioned no-alloc scratch)
// ---------------------------------------------------------------------------
__device__ __align__(16) float g_wx[(size_t)Bn * Sn * 4 * Hn];   // [b*S+s][4H]
__device__ __align__(16) float g_state[2 * Hn * Bn * 2];         // ping-pong, float2(h,c), k-major
__device__ unsigned g_count = 0;
__device__ unsigned g_sense = 0;

// ---------------------------------------------------------------------------
// SGEMM with bias: C[M,N] = A[M,K] @ B[K,N] + bias[N]   (unchanged, passing)
// ---------------------------------------------------------------------------
__global__ void __launch_bounds__(256)
sgemm_bias(const float* __restrict__ A, const float* __restrict__ Bm,
           const float* __restrict__ bias, float* __restrict__ C,
           int M, int N, int K)
{
    if (C == nullptr) C = g_wx;

    __shared__ float As[16][132];
    __shared__ float Bs[16][132];

    const int tid = threadIdx.x;
    const int tx = tid & 15;
    const int ty = tid >> 4;
    const int m0 = blockIdx.y * 128;
    const int n0 = blockIdx.x * 128;

    float acc[8][8];
#pragma unroll
    for (int i = 0; i < 8; i++)
#pragma unroll
        for (int j = 0; j < 8; j++) acc[i][j] = 0.0f;

    const int ar = tid >> 1;
    const int ah = tid & 1;
    const float* Abase = A + (size_t)(m0 + ar) * K + ah * 8;
    const int bk = tid >> 5;
    const int bc = (tid & 31) * 4;

    for (int k0 = 0; k0 < K; k0 += 16) {
        float4 a0 = *reinterpret_cast<const float4*>(Abase + k0);
        float4 a1 = *reinterpret_cast<const float4*>(Abase + k0 + 4);
        As[ah * 8 + 0][ar] = a0.x; As[ah * 8 + 1][ar] = a0.y;
        As[ah * 8 + 2][ar] = a0.z; As[ah * 8 + 3][ar] = a0.w;
        As[ah * 8 + 4][ar] = a1.x; As[ah * 8 + 5][ar] = a1.y;
        As[ah * 8 + 6][ar] = a1.z; As[ah * 8 + 7][ar] = a1.w;
#pragma unroll
        for (int p = 0; p < 16; p += 8) {
            float4 bv = *reinterpret_cast<const float4*>(
                Bm + (size_t)(k0 + bk + p) * N + n0 + bc);
            *reinterpret_cast<float4*>(&Bs[bk + p][bc]) = bv;
        }
        __syncthreads();

#pragma unroll
        for (int k = 0; k < 16; k++) {
            float ra[8], rb[8];
            *reinterpret_cast<float4*>(ra)     = *reinterpret_cast<const float4*>(&As[k][ty * 8]);
            *reinterpret_cast<float4*>(ra + 4) = *reinterpret_cast<const float4*>(&As[k][ty * 8 + 4]);
            *reinterpret_cast<float4*>(rb)     = *reinterpret_cast<const float4*>(&Bs[k][tx * 8]);
            *reinterpret_cast<float4*>(rb + 4) = *reinterpret_cast<const float4*>(&Bs[k][tx * 8 + 4]);
#pragma unroll
            for (int i = 0; i < 8; i++)
#pragma unroll
                for (int j = 0; j < 8; j++)
                    acc[i][j] = fmaf(ra[i], rb[j], acc[i][j]);
        }
        __syncthreads();
    }

    float bb[8];
#pragma unroll
    for (int j = 0; j < 8; j++) bb[j] = bias[n0 + tx * 8 + j];

#pragma unroll
    for (int i = 0; i < 8; i++) {
        const size_t row = (size_t)(m0 + ty * 8 + i) * N + n0 + tx * 8;
        float4 o0, o1;
        o0.x = acc[i][0] + bb[0]; o0.y = acc[i][1] + bb[1];
        o0.z = acc[i][2] + bb[2]; o0.w = acc[i][3] + bb[3];
        o1.x = acc[i][4] + bb[4]; o1.y = acc[i][5] + bb[5];
        o1.z = acc[i][6] + bb[6]; o1.w = acc[i][7] + bb[7];
        *reinterpret_cast<float4*>(&C[row])     = o0;
        *reinterpret_cast<float4*>(&C[row + 4]) = o1;
    }
}

// ---------------------------------------------------------------------------
// f32x2 packed helpers (sm_103a)
// ---------------------------------------------------------------------------
__device__ __forceinline__ unsigned long long pack2(float v) {
    unsigned long long r;
    asm("mov.b64 %0, {%1, %1};" : "=l"(r) : "f"(v));
    return r;
}
__device__ __forceinline__ void fma2(unsigned long long& d,
                                     unsigned long long a, unsigned long long b) {
    asm("fma.rn.f32x2 %0, %1, %2, %0;" : "+l"(d) : "l"(a), "l"(b));
}
__device__ __forceinline__ float2 unpack2(unsigned long long v) {
    float2 r;
    asm("mov.b64 {%0, %1}, %2;" : "=f"(r.x), "=f"(r.y) : "l"(v));
    return r;
}

__device__ __forceinline__ float sigf(float x) { return 1.0f / (1.0f + __expf(-x)); }

__device__ __forceinline__ void grid_barrier(unsigned& lsense)
{
    __threadfence();
    __syncthreads();
    if (threadIdx.x == 0) {
        const unsigned target = lsense ^ 1u;
        if (atomicAdd(&g_count, 1u) == (unsigned)(NCTA - 1)) {
            g_count = 0;
            __threadfence();
            *((volatile unsigned*)&g_sense) = target;
        } else {
            while (*((volatile unsigned*)&g_sense) != target) { }
        }
    }
    __syncthreads();
    lsense ^= 1u;
}

// ---------------------------------------------------------------------------
// Persistent recurrence: 128 CTAs x 256 threads.
// CTA cid owns hidden columns j = cid*4 .. cid*4+3.
// Thread = (b = tid&127, kg = tid>>7) computes all 4 j over its K-half with
// f32x2-packed FMAs. State loads are chunked + double-buffered (MLP=16) so
// the ~300-cycle L2 latency is fully covered by each chunk's 160 FFMA2s.
// ---------------------------------------------------------------------------

// Load one 16-k chunk of state (float2 h,c per k) into a register buffer.
#define LOAD_CHUNK(BUF, CH) do {                                          \
    const int kn_ = kb0 + (CH) * 16;                                      \
    _Pragma("unroll")                                                     \
    for (int i_ = 0; i_ < 16; i_++)                                       \
        BUF[i_] = __ldcg(st + (size_t)(kn_ + i_) * 128 + b);              \
} while (0)

// Consume one 16-k chunk: 8 k-pairs x 20 fma2.
#define COMPUTE_CHUNK(BUF, CH) do {                                       \
    _Pragma("unroll")                                                     \
    for (int t_ = 0; t_ < 8; t_++) {                                      \
        const int kp_ = kp0 + (CH) * 8 + t_;                              \
        const unsigned long long hh0 = pack2(BUF[2 * t_].x);              \
        const unsigned long long cc0 = pack2(BUF[2 * t_].y);              \
        const unsigned long long hh1 = pack2(BUF[2 * t_ + 1].x);          \
        const unsigned long long cc1 = pack2(BUF[2 * t_ + 1].y);          \
        _Pragma("unroll")                                                 \
        for (int g_ = 0; g_ < 4; g_++) {                                  \
            _Pragma("unroll")                                             \
            for (int p_ = 0; p_ < 2; p_++) {                              \
                ulonglong2 w = *reinterpret_cast<const ulonglong2*>(      \
                    Us2 + (size_t)(((g_ * 2 + p_) * 256 + kp_) * 2));     \
                fma2(acc[g_ * 2 + p_], hh0, w.x);                         \
                fma2(acc[g_ * 2 + p_], hh1, w.y);                         \
            }                                                             \
        }                                                                 \
        _Pragma("unroll")                                                 \
        for (int p_ = 0; p_ < 2; p_++) {                                  \
            ulonglong2 w = *reinterpret_cast<const ulonglong2*>(          \
                Wd2 + (size_t)((p_ * 256 + kp_) * 2));                    \
            fma2(acc[8 + p_], cc0, w.x);                                  \
            fma2(acc[8 + p_], cc1, w.y);                                  \
        }                                                                 \
    }                                                                     \
} while (0)

__global__ void __launch_bounds__(256, 1)
tlstm_recur(const float* __restrict__ U_all, const float* __restrict__ b_u,
            const float* __restrict__ W_d,  const float* __restrict__ b_d,
            const float* __restrict__ td,
            float* __restrict__ hs_out, float* __restrict__ cs_out)
{
    extern __shared__ unsigned long long smem_u[];
    unsigned long long* Us2 = smem_u;          // [ (g*2+p)*256 + kp ] x {k-even,k-odd} : 4096 ull
    unsigned long long* Wd2 = smem_u + 4096;   // [ p*256 + kp ] x {k-even,k-odd}       : 1024 ull
    float* red  = (float*)(smem_u + 5120);     // [b][20] partials : 2560 floats
    float* bu_s = red + 2560;                  // [g*4 + j] : 16
    float* bd_s = bu_s + 16;                   // [j] : 4

    const int tid = threadIdx.x;
    const int cid = blockIdx.x;
    const int b   = tid & 127;
    const int kg  = tid >> 7;          // which K-half

    // ---- one-time staging: packed weight pairs into SMEM ----
    {
        float* UsF = (float*)Us2;
        for (int i = tid; i < 8192; i += 256) {
            const int jj = i & 1;
            const int h  = (i >> 1) & 1;
            const int kp = (i >> 2) & 255;
            const int p  = (i >> 10) & 1;
            const int g  = i >> 11;
            const int k  = kp * 2 + h;
            UsF[i] = U_all[(size_t)k * 2048 + g * 512 + cid * 4 + p * 2 + jj];
        }
        float* WdF = (float*)Wd2;
        for (int i = tid; i < 2048; i += 256) {
            const int jj = i & 1;
            const int h  = (i >> 1) & 1;
            const int kp = (i >> 2) & 255;
            const int p  = i >> 10;
            const int k  = kp * 2 + h;
            WdF[i] = W_d[(size_t)k * 512 + cid * 4 + p * 2 + jj];
        }
        if (tid < 16) bu_s[tid] = b_u[(tid >> 2) * 512 + cid * 4 + (tid & 3)];
        if (tid < 4)  bd_s[tid] = b_d[cid * 4 + tid];
    }

    // zero ping buffer 0 (disjoint slice per CTA)
    {
        float2* stz = reinterpret_cast<float2*>(g_state);
        for (int i = tid; i < 512; i += 256)
            stz[cid * 512 + i] = make_float2(0.f, 0.f);
    }

    unsigned lsense = *((volatile unsigned*)&g_sense);
    grid_barrier(lsense);

    const int kp0 = kg * 128;          // first k-pair of this thread's half
    const int kb0 = kp0 * 2;           // first k

    for (int s = 0; s < Sn; s++) {
        if (s) grid_barrier(lsense);

        const float2* st = reinterpret_cast<const float2*>(g_state) + (size_t)(s & 1) * (Hn * Bn);
        float2*      stn = reinterpret_cast<float2*>(g_state) + (size_t)((s & 1) ^ 1) * (Hn * Bn);

        // ---- prefetch step operands (consumed after the dot loop) ----
        const float* wxb = g_wx + ((size_t)b * Sn + s) * 2048 + cid * 4;
        float wxa[4][4];
#pragma unroll
        for (int g = 0; g < 4; g++) {
            float4 v = __ldg(reinterpret_cast<const float4*>(wxb + g * 512));
            wxa[g][0] = v.x; wxa[g][1] = v.y; wxa[g][2] = v.z; wxa[g][3] = v.w;
        }
        float c_old[4];
#pragma unroll
        for (int j = 0; j < 4; j++)
            c_old[j] = __ldcg(st + (size_t)(cid * 4 + j) * 128 + b).y;
        const float tdv = __ldg(td + (size_t)b * Sn + s);

        // ---- dot products over this thread's K-half (chunked, MLP=16) ----
        unsigned long long acc[10];
#pragma unroll
        for (int i = 0; i < 10; i++) acc[i] = 0ull;

        float2 bufA[16], bufB[16];
        LOAD_CHUNK(bufA, 0);

#pragma unroll 1
        for (int ch = 0; ch < 16; ch += 2) {
            LOAD_CHUNK(bufB, ch + 1);
            COMPUTE_CHUNK(bufA, ch);
            if (ch + 2 < 16) LOAD_CHUNK(bufA, ch + 2);
            COMPUTE_CHUNK(bufB, ch + 1);
        }

        // ---- reduce the two K-halves via SMEM ----
        if (kg == 1) {
#pragma unroll
            for (int i = 0; i < 10; i++) {
                float2 r = unpack2(acc[i]);
                red[b * 20 + i * 2]     = r.x;
                red[b * 20 + i * 2 + 1] = r.y;
            }
        }
        __syncthreads();

        if (kg == 0) {
            float G[5][4];
#pragma unroll
            for (int i = 0; i < 10; i++) {
                float2 mine = unpack2(acc[i]);
                const int g = i >> 1;
                const int p = i & 1;
                G[g][p * 2 + 0] = mine.x + red[b * 20 + i * 2];
                G[g][p * 2 + 1] = mine.y + red[b * 20 + i * 2 + 1];
            }

            float hv[4], cv[4];
#pragma unroll
            for (int j = 0; j < 4; j++) {
                const float cst  = sigf(G[4][j] + bd_s[j]);
                const float cadj = c_old[j] - cst + cst * tdv;
                const float ff   = sigf(wxa[0][j] + G[0][j] + bu_s[j]);
                const float ii   = sigf(wxa[1][j] + G[1][j] + bu_s[4 + j]);
                const float oo   = sigf(wxa[2][j] + G[2][j] + bu_s[8 + j]);
                const float gg   = tanhf(wxa[3][j] + G[3][j] + bu_s[12 + j]);
                const float cn   = ff * cadj + ii * gg;
                const float hn   = oo * tanhf(cn);
                cv[j] = cn; hv[j] = hn;
                stn[(size_t)(cid * 4 + j) * 128 + b] = make_float2(hn, cn);
            }

            const size_t ob = ((size_t)b * Sn + s) * Hn + cid * 4;
            *reinterpret_cast<float4*>(hs_out + ob) = make_float4(hv[0], hv[1], hv[2], hv[3]);
            *reinterpret_cast<float4*>(cs_out + ob) = make_float4(cv[0], cv[1], cv[2], cv[3]);
        }
    }
}

// ---------------------------------------------------------------------------
// Launch
// ---------------------------------------------------------------------------
extern "C" void kernel_launch(void* const* d_in, const int* in_sizes, int n_in,
                              void* d_out, int out_size)
{
    const float* inputs     = (const float*)d_in[0];
    const float* time_diffs = (const float*)d_in[1];
    // d_in[2] = seq_lens (unused by reference)
    const float* W_all      = (const float*)d_in[3];
    const float* b_all      = (const float*)d_in[4];
    const float* U_all      = (const float*)d_in[5];
    const float* b_u        = (const float*)d_in[6];
    const float* W_d        = (const float*)d_in[7];
    const float* b_d        = (const float*)d_in[8];
    const float* W_out      = (const float*)d_in[9];
    const float* b_out      = (const float*)d_in[10];

    float* out = (float*)d_out;                        // [B,S,O]
    float* hs  = out + (size_t)Bn * Sn * On;           // [B,S,H]
    float* cs  = hs  + (size_t)Bn * Sn * Hn;           // [B,S,H]

    const int M = Bn * Sn;  // 65536

    // GEMM1: Wx = inputs @ W_all + b_all  -> g_wx
    {
        dim3 grid((4 * Hn) / 128, M / 128);
        sgemm_bias<<<grid, 256>>>(inputs, W_all, b_all, nullptr, M, 4 * Hn, Dn);
    }

    // Recurrence: persistent grid, grid-wide barrier per step
    {
        const int shmem = 5120 * 8 + 2560 * 4 + 20 * 4;  // 51280 B
        cudaFuncSetAttribute(tlstm_recur,
                             cudaFuncAttributeMaxDynamicSharedMemorySize, shmem);
        tlstm_recur<<<NCTA, 256, shmem>>>(U_all, b_u, W_d, b_d, time_diffs, hs, cs);
    }

    // GEMM2: outputs = hs @ W_out + b_out
    {
        dim3 grid(On / 128, M / 128);
        sgemm_bias<<<grid, 256>>>(hs, W_out, b_out, out, M, On, Hn);
    }
}

// round 12
// speedup vs baseline: 1.1198x; 1.1143x over previous
#include <cuda_runtime.h>
#include <cstddef>

#define Bn 128
#define Sn 512
#define Dn 256
#define Hn 512
#define On 256
#define NCTA 128

// ---------------------------------------------------------------------------
// Device scratch (static __device__ globals — the sanctioned no-alloc scratch)
// ---------------------------------------------------------------------------
__device__ __align__(16) float g_wx[(size_t)Bn * Sn * 4 * Hn];   // [b*S+s][4H]
__device__ __align__(16) float g_state[2 * Hn * Bn * 2];         // ping-pong, float2(h,c), k-major
__device__ unsigned g_count = 0;
__device__ unsigned g_sense = 0;

// ---------------------------------------------------------------------------
// f32x2 packed helpers (sm_103a)
// ---------------------------------------------------------------------------
__device__ __forceinline__ unsigned long long pack2(float v) {
    unsigned long long r;
    asm("mov.b64 %0, {%1, %1};" : "=l"(r) : "f"(v));
    return r;
}
__device__ __forceinline__ void fma2(unsigned long long& d,
                                     unsigned long long a, unsigned long long b) {
    asm("fma.rn.f32x2 %0, %1, %2, %0;" : "+l"(d) : "l"(a), "l"(b));
}
__device__ __forceinline__ float2 unpack2(unsigned long long v) {
    float2 r;
    asm("mov.b64 {%0, %1}, %2;" : "=f"(r.x), "=f"(r.y) : "l"(v));
    return r;
}

// ---------------------------------------------------------------------------
// SGEMM with bias (f32x2 accumulators): C[M,N] = A[M,K] @ B[K,N] + bias[N]
// BM=BN=128, BK=16, 256 threads, 8x8 per thread as 8 rows x 4 f32x2 pairs.
// ---------------------------------------------------------------------------
__global__ void __launch_bounds__(256)
sgemm_bias(const float* __restrict__ A, const float* __restrict__ Bm,
           const float* __restrict__ bias, float* __restrict__ C,
           int M, int N, int K)
{
    if (C == nullptr) C = g_wx;

    __shared__ float As[16][132];
    __shared__ float Bs[16][132];

    const int tid = threadIdx.x;
    const int tx = tid & 15;
    const int ty = tid >> 4;
    const int m0 = blockIdx.y * 128;
    const int n0 = blockIdx.x * 128;

    unsigned long long acc2[8][4];
#pragma unroll
    for (int i = 0; i < 8; i++)
#pragma unroll
        for (int p = 0; p < 4; p++) acc2[i][p] = 0ull;

    const int ar = tid >> 1;
    const int ah = tid & 1;
    const float* Abase = A + (size_t)(m0 + ar) * K + ah * 8;
    const int bk = tid >> 5;
    const int bc = (tid & 31) * 4;

    for (int k0 = 0; k0 < K; k0 += 16) {
        float4 a0 = *reinterpret_cast<const float4*>(Abase + k0);
        float4 a1 = *reinterpret_cast<const float4*>(Abase + k0 + 4);
        As[ah * 8 + 0][ar] = a0.x; As[ah * 8 + 1][ar] = a0.y;
        As[ah * 8 + 2][ar] = a0.z; As[ah * 8 + 3][ar] = a0.w;
        As[ah * 8 + 4][ar] = a1.x; As[ah * 8 + 5][ar] = a1.y;
        As[ah * 8 + 6][ar] = a1.z; As[ah * 8 + 7][ar] = a1.w;
#pragma unroll
        for (int p = 0; p < 16; p += 8) {
            float4 bv = *reinterpret_cast<const float4*>(
                Bm + (size_t)(k0 + bk + p) * N + n0 + bc);
            *reinterpret_cast<float4*>(&Bs[bk + p][bc]) = bv;
        }
        __syncthreads();

#pragma unroll
        for (int k = 0; k < 16; k++) {
            float ra[8];
            *reinterpret_cast<float4*>(ra)     = *reinterpret_cast<const float4*>(&As[k][ty * 8]);
            *reinterpret_cast<float4*>(ra + 4) = *reinterpret_cast<const float4*>(&As[k][ty * 8 + 4]);
            ulonglong2 u0 = *reinterpret_cast<const ulonglong2*>(&Bs[k][tx * 8]);
            ulonglong2 u1 = *reinterpret_cast<const ulonglong2*>(&Bs[k][tx * 8 + 4]);
#pragma unroll
            for (int i = 0; i < 8; i++) {
                const unsigned long long rah = pack2(ra[i]);
                fma2(acc2[i][0], rah, u0.x);
                fma2(acc2[i][1], rah, u0.y);
                fma2(acc2[i][2], rah, u1.x);
                fma2(acc2[i][3], rah, u1.y);
            }
        }
        __syncthreads();
    }

    float bb[8];
#pragma unroll
    for (int j = 0; j < 8; j++) bb[j] = bias[n0 + tx * 8 + j];

#pragma unroll
    for (int i = 0; i < 8; i++) {
        float c[8];
#pragma unroll
        for (int p = 0; p < 4; p++) {
            float2 v = unpack2(acc2[i][p]);
            c[2 * p]     = v.x + bb[2 * p];
            c[2 * p + 1] = v.y + bb[2 * p + 1];
        }
        const size_t row = (size_t)(m0 + ty * 8 + i) * N + n0 + tx * 8;
        *reinterpret_cast<float4*>(&C[row])     = make_float4(c[0], c[1], c[2], c[3]);
        *reinterpret_cast<float4*>(&C[row + 4]) = make_float4(c[4], c[5], c[6], c[7]);
    }
}

// ---------------------------------------------------------------------------
__device__ __forceinline__ float sigf(float x) { return 1.0f / (1.0f + __expf(-x)); }

__device__ __forceinline__ void grid_barrier(unsigned& lsense)
{
    __threadfence();
    __syncthreads();
    if (threadIdx.x == 0) {
        const unsigned target = lsense ^ 1u;
        if (atomicAdd(&g_count, 1u) == (unsigned)(NCTA - 1)) {
            g_count = 0;
            __threadfence();
            *((volatile unsigned*)&g_sense) = target;
        } else {
            while (*((volatile unsigned*)&g_sense) != target) { }
        }
    }
    __syncthreads();
    lsense ^= 1u;
}

// ---------------------------------------------------------------------------
// Persistent recurrence: 128 CTAs = 32 j-blocks x 4 b-blocks; CTA owns
// 16 hidden columns x 32 batches. Weights (160 KB) live in SMEM.
// Thread = (bloc = tid&31, jh = (tid>>5)&1, kg = tid>>6). Each thread
// computes 8 j (4 f32x2 pairs) x 5 gates over a K-quarter (128 k), with
// chunked double-buffered state loads. 4-way k reduction via SMEM.
// L2 state traffic: 16 MB/step (4x less than the 1D-j partition).
// ---------------------------------------------------------------------------

#define LOAD_CHUNK(BUF, CH) do {                                          \
    const int kb_ = kg * 128 + (CH) * 16;                                 \
    _Pragma("unroll")                                                     \
    for (int i_ = 0; i_ < 16; i_++)                                       \
        BUF[i_] = __ldcg(st + (size_t)(kb_ + i_) * 128 + bglob);          \
} while (0)

#define COMPUTE_CHUNK(BUF, CH) do {                                      \
    _Pragma("unroll")                                                     \
    for (int t_ = 0; t_ < 8; t_++) {                                      \
        const int kp_ = kg * 64 + (CH) * 8 + t_;                          \
        const unsigned long long hh0 = pack2(BUF[2 * t_].x);              \
        const unsigned long long cc0 = pack2(BUF[2 * t_].y);              \
        const unsigned long long hh1 = pack2(BUF[2 * t_ + 1].x);          \
        const unsigned long long cc1 = pack2(BUF[2 * t_ + 1].y);          \
        _Pragma("unroll")                                                 \
        for (int jp_ = 0; jp_ < 4; jp_++) {                               \
            _Pragma("unroll")                                             \
            for (int g_ = 0; g_ < 4; g_++) {                              \
                ulonglong2 w = Us2[((jh * 4 + jp_) * 4 + g_) * 256 + kp_];\
                fma2(acc[jp_ * 5 + g_], hh0, w.x);                        \
                fma2(acc[jp_ * 5 + g_], hh1, w.y);                        \
            }                                                             \
        }                                                                 \
        _Pragma("unroll")                                                 \
        for (int jp_ = 0; jp_ < 4; jp_++) {                               \
            ulonglong2 w = Wd2[(jh * 4 + jp_) * 256 + kp_];               \
            fma2(acc[jp_ * 5 + 4], cc0, w.x);                             \
            fma2(acc[jp_ * 5 + 4], cc1, w.y);                             \
        }                                                                 \
    }                                                                     \
} while (0)

__global__ void __launch_bounds__(256, 1)
tlstm_recur(const float* __restrict__ U_all, const float* __restrict__ b_u,
            const float* __restrict__ W_d,  const float* __restrict__ b_d,
            const float* __restrict__ td,
            float* __restrict__ hs_out, float* __restrict__ cs_out)
{
    extern __shared__ unsigned long long smem_u[];
    ulonglong2* Us2 = (ulonglong2*)smem_u;                    // 8192 ull2 = 128 KB
    ulonglong2* Wd2 = (ulonglong2*)(smem_u + 16384);          // 2048 ull2 = 32 KB
    float* red  = (float*)(smem_u + 20480);                   // 10240 floats = 40 KB
    float* bu_s = red + 10240;                                // [g*16 + jl] : 64
    float* bd_s = bu_s + 64;                                  // [jl] : 16

    const int tid  = threadIdx.x;
    const int cid  = blockIdx.x;
    const int jb   = cid >> 2;          // j-block (0..31): j = jb*16 ..
    const int bb   = cid & 3;           // b-block (0..3):  b = bb*32 ..

    const int bloc = tid & 31;
    const int jh   = (tid >> 5) & 1;
    const int kg   = tid >> 6;
    const int bglob = bb * 32 + bloc;

    // ---- one-time staging: packed weight pairs into SMEM ----
    {
        float* UsF = (float*)Us2;
        for (int i = tid; i < 32768; i += 256) {
            const int lane = i & 1;
            const int h    = (i >> 1) & 1;
            const int kp   = (i >> 2) & 255;
            const int g    = (i >> 10) & 3;
            const int jp   = (i >> 12) & 3;
            const int jhh  = (i >> 14) & 1;
            const int k    = kp * 2 + h;
            const int j    = jb * 16 + jhh * 8 + jp * 2 + lane;
            UsF[i] = U_all[(size_t)k * 2048 + g * 512 + j];
        }
        float* WdF = (float*)Wd2;
        for (int i = tid; i < 8192; i += 256) {
            const int lane = i & 1;
            const int h    = (i >> 1) & 1;
            const int kp   = (i >> 2) & 255;
            const int jp   = (i >> 10) & 3;
            const int jhh  = (i >> 12) & 1;
            const int j    = jb * 16 + jhh * 8 + jp * 2 + lane;
            WdF[i] = W_d[(size_t)(kp * 2 + h) * 512 + j];
        }
        if (tid < 64) bu_s[tid] = b_u[(tid >> 4) * 512 + jb * 16 + (tid & 15)];
        if (tid < 16) bd_s[tid] = b_d[jb * 16 + tid];
    }

    // zero ping buffer 0 (disjoint slice per CTA; 128 CTAs cover 65536 float2)
    {
        float2* stz = reinterpret_cast<float2*>(g_state);
        for (int i = tid; i < 512; i += 256)
            stz[cid * 512 + i] = make_float2(0.f, 0.f);
    }

    unsigned lsense = *((volatile unsigned*)&g_sense);
    grid_barrier(lsense);

    // final-phase mapping (independent of dot-loop mapping)
    const int bo    = tid >> 3;             // 0..31
    const int jq    = tid & 7;              // j-pair within 16
    const int jh2   = jq >> 2;
    const int jp2   = jq & 3;
    const int jglob = jb * 16 + jq * 2;
    const int bg2   = bb * 32 + bo;

    for (int s = 0; s < Sn; s++) {
        if (s) grid_barrier(lsense);

        const float2* st = reinterpret_cast<const float2*>(g_state) + (size_t)(s & 1) * (Hn * Bn);
        float2*      stn = reinterpret_cast<float2*>(g_state) + (size_t)((s & 1) ^ 1) * (Hn * Bn);

        // ---- prefetch final-phase operands (consumed after the dot loop) ----
        const float* wxb = g_wx + ((size_t)bg2 * Sn + s) * 2048 + jglob;
        const float2 wxF = *reinterpret_cast<const float2*>(wxb + 0 * 512);
        const float2 wxI = *reinterpret_cast<const float2*>(wxb + 1 * 512);
        const float2 wxO = *reinterpret_cast<const float2*>(wxb + 2 * 512);
        const float2 wxG = *reinterpret_cast<const float2*>(wxb + 3 * 512);
        const float  co0 = __ldcg(st + (size_t)jglob * 128 + bg2).y;
        const float  co1 = __ldcg(st + (size_t)(jglob + 1) * 128 + bg2).y;
        const float  tdv = __ldg(td + (size_t)bg2 * Sn + s);

        // ---- dot products over this thread's K-quarter (chunked, MLP=16) ----
        unsigned long long acc[20];
#pragma unroll
        for (int i = 0; i < 20; i++) acc[i] = 0ull;

        float2 bufA[16], bufB[16];
        LOAD_CHUNK(bufA, 0);

#pragma unroll 1
        for (int ch = 0; ch < 8; ch += 2) {
            LOAD_CHUNK(bufB, ch + 1);
            COMPUTE_CHUNK(bufA, ch);
            if (ch + 2 < 8) LOAD_CHUNK(bufA, ch + 2);
            COMPUTE_CHUNK(bufB, ch + 1);
        }

        // ---- write partials: red[(kg*32+bloc)*2 + jh][40] ----
        {
            float2* pr = reinterpret_cast<float2*>(
                red + (size_t)(((kg * 32 + bloc) * 2 + jh) * 40));
#pragma unroll
            for (int i = 0; i < 20; i++) pr[i] = unpack2(acc[i]);
        }
        __syncthreads();

        // ---- final phase: sum 4 k-quarters, apply gates, write outputs ----
        {
            float2 G[5];
#pragma unroll
            for (int g = 0; g < 5; g++) {
                float2 sum = make_float2(0.f, 0.f);
#pragma unroll
                for (int q = 0; q < 4; q++) {
                    float2 v = *reinterpret_cast<const float2*>(
                        red + (size_t)(((q * 32 + bo) * 2 + jh2) * 40 + (jp2 * 5 + g) * 2));
                    sum.x += v.x; sum.y += v.y;
                }
                G[g] = sum;
            }

            const int jl = jq * 2;
            // lane 0
            const float cst0  = sigf(G[4].x + bd_s[jl]);
            const float cadj0 = co0 - cst0 + cst0 * tdv;
            const float ff0   = sigf(wxF.x + G[0].x + bu_s[jl]);
            const float ii0   = sigf(wxI.x + G[1].x + bu_s[16 + jl]);
            const float oo0   = sigf(wxO.x + G[2].x + bu_s[32 + jl]);
            const float gg0   = tanhf(wxG.x + G[3].x + bu_s[48 + jl]);
            const float cn0   = ff0 * cadj0 + ii0 * gg0;
            const float hn0   = oo0 * tanhf(cn0);
            // lane 1
            const float cst1  = sigf(G[4].y + bd_s[jl + 1]);
            const float cadj1 = co1 - cst1 + cst1 * tdv;
            const float ff1   = sigf(wxF.y + G[0].y + bu_s[jl + 1]);
            const float ii1   = sigf(wxI.y + G[1].y + bu_s[16 + jl + 1]);
            const float oo1   = sigf(wxO.y + G[2].y + bu_s[32 + jl + 1]);
            const float gg1   = tanhf(wxG.y + G[3].y + bu_s[48 + jl + 1]);
            const float cn1   = ff1 * cadj1 + ii1 * gg1;
            const float hn1   = oo1 * tanhf(cn1);

            stn[(size_t)jglob * 128 + bg2]       = make_float2(hn0, cn0);
            stn[(size_t)(jglob + 1) * 128 + bg2] = make_float2(hn1, cn1);

            const size_t ob = ((size_t)bg2 * Sn + s) * Hn + jglob;
            *reinterpret_cast<float2*>(hs_out + ob) = make_float2(hn0, hn1);
            *reinterpret_cast<float2*>(cs_out + ob) = make_float2(cn0, cn1);
        }
    }
}

// ---------------------------------------------------------------------------
// Launch
// ---------------------------------------------------------------------------
extern "C" void kernel_launch(void* const* d_in, const int* in_sizes, int n_in,
                              void* d_out, int out_size)
{
    const float* inputs     = (const float*)d_in[0];
    const float* time_diffs = (const float*)d_in[1];
    // d_in[2] = seq_lens (unused by reference)
    const float* W_all      = (const float*)d_in[3];
    const float* b_all      = (const float*)d_in[4];
    const float* U_all      = (const float*)d_in[5];
    const float* b_u        = (const float*)d_in[6];
    const float* W_d        = (const float*)d_in[7];
    const float* b_d        = (const float*)d_in[8];
    const float* W_out      = (const float*)d_in[9];
    const float* b_out      = (const float*)d_in[10];

    float* out = (float*)d_out;                        // [B,S,O]
    float* hs  = out + (size_t)Bn * Sn * On;           // [B,S,H]
    float* cs  = hs  + (size_t)Bn * Sn * Hn;           // [B,S,H]

    const int M = Bn * Sn;  // 65536

    // GEMM1: Wx = inputs @ W_all + b_all  -> g_wx
    {
        dim3 grid((4 * Hn) / 128, M / 128);
        sgemm_bias<<<grid, 256>>>(inputs, W_all, b_all, nullptr, M, 4 * Hn, Dn);
    }

    // Recurrence: persistent grid, grid-wide barrier per step
    {
        const int shmem = 20480 * 8 + 10240 * 4 + 80 * 4;   // 205120 B
        cudaFuncSetAttribute(tlstm_recur,
                             cudaFuncAttributeMaxDynamicSharedMemorySize, shmem);
        tlstm_recur<<<NCTA, 256, shmem>>>(U_all, b_u, W_d, b_d, time_diffs, hs, cs);
    }

    // GEMM2: outputs = hs @ W_out + b_out
    {
        dim3 grid(On / 128, M / 128);
        sgemm_bias<<<grid, 256>>>(hs, W_out, b_out, out, M, On, Hn);
    }
}

// round 13
// speedup vs baseline: 1.1208x; 1.0009x over previous
#include <cuda_runtime.h>
#include <cstddef>

#define Bn 128
#define Sn 512
#define Dn 256
#define Hn 512
#define On 256
#define NCTA 128

// ---------------------------------------------------------------------------
// Device scratch (static __device__ globals — the sanctioned no-alloc scratch)
// ---------------------------------------------------------------------------
__device__ __align__(16) float g_wx[(size_t)Bn * Sn * 4 * Hn];   // [b*S+s][4H]
__device__ __align__(16) float g_state[2 * Hn * Bn * 2];         // ping-pong, float2(h,c), k-major
__device__ unsigned g_count = 0;
__device__ unsigned g_sense = 0;

// ---------------------------------------------------------------------------
// f32x2 packed helpers (sm_103a)
// ---------------------------------------------------------------------------
__device__ __forceinline__ unsigned long long pack2(float v) {
    unsigned long long r;
    asm("mov.b64 %0, {%1, %1};" : "=l"(r) : "f"(v));
    return r;
}
__device__ __forceinline__ void fma2(unsigned long long& d,
                                     unsigned long long a, unsigned long long b) {
    asm("fma.rn.f32x2 %0, %1, %2, %0;" : "+l"(d) : "l"(a), "l"(b));
}
__device__ __forceinline__ float2 unpack2(unsigned long long v) {
    float2 r;
    asm("mov.b64 {%0, %1}, %2;" : "=f"(r.x), "=f"(r.y) : "l"(v));
    return r;
}

// ---------------------------------------------------------------------------
// SGEMM with bias (f32x2 accumulators): C[M,N] = A[M,K] @ B[K,N] + bias[N]
// BM=BN=128, BK=16, 256 threads, 8x8 per thread as 8 rows x 4 f32x2 pairs.
// ---------------------------------------------------------------------------
__global__ void __launch_bounds__(256)
sgemm_bias(const float* __restrict__ A, const float* __restrict__ Bm,
           const float* __restrict__ bias, float* __restrict__ C,
           int M, int N, int K)
{
    if (C == nullptr) C = g_wx;

    __shared__ float As[16][132];
    __shared__ float Bs[16][132];

    const int tid = threadIdx.x;
    const int tx = tid & 15;
    const int ty = tid >> 4;
    const int m0 = blockIdx.y * 128;
    const int n0 = blockIdx.x * 128;

    unsigned long long acc2[8][4];
#pragma unroll
    for (int i = 0; i < 8; i++)
#pragma unroll
        for (int p = 0; p < 4; p++) acc2[i][p] = 0ull;

    const int ar = tid >> 1;
    const int ah = tid & 1;
    const float* Abase = A + (size_t)(m0 + ar) * K + ah * 8;
    const int bk = tid >> 5;
    const int bc = (tid & 31) * 4;

    for (int k0 = 0; k0 < K; k0 += 16) {
        float4 a0 = *reinterpret_cast<const float4*>(Abase + k0);
        float4 a1 = *reinterpret_cast<const float4*>(Abase + k0 + 4);
        As[ah * 8 + 0][ar] = a0.x; As[ah * 8 + 1][ar] = a0.y;
        As[ah * 8 + 2][ar] = a0.z; As[ah * 8 + 3][ar] = a0.w;
        As[ah * 8 + 4][ar] = a1.x; As[ah * 8 + 5][ar] = a1.y;
        As[ah * 8 + 6][ar] = a1.z; As[ah * 8 + 7][ar] = a1.w;
#pragma unroll
        for (int p = 0; p < 16; p += 8) {
            float4 bv = *reinterpret_cast<const float4*>(
                Bm + (size_t)(k0 + bk + p) * N + n0 + bc);
            *reinterpret_cast<float4*>(&Bs[bk + p][bc]) = bv;
        }
        __syncthreads();

#pragma unroll
        for (int k = 0; k < 16; k++) {
            float ra[8];
            *reinterpret_cast<float4*>(ra)     = *reinterpret_cast<const float4*>(&As[k][ty * 8]);
            *reinterpret_cast<float4*>(ra + 4) = *reinterpret_cast<const float4*>(&As[k][ty * 8 + 4]);
            ulonglong2 u0 = *reinterpret_cast<const ulonglong2*>(&Bs[k][tx * 8]);
            ulonglong2 u1 = *reinterpret_cast<const ulonglong2*>(&Bs[k][tx * 8 + 4]);
#pragma unroll
            for (int i = 0; i < 8; i++) {
                const unsigned long long rah = pack2(ra[i]);
                fma2(acc2[i][0], rah, u0.x);
                fma2(acc2[i][1], rah, u0.y);
                fma2(acc2[i][2], rah, u1.x);
                fma2(acc2[i][3], rah, u1.y);
            }
        }
        __syncthreads();
    }

    float bb[8];
#pragma unroll
    for (int j = 0; j < 8; j++) bb[j] = bias[n0 + tx * 8 + j];

#pragma unroll
    for (int i = 0; i < 8; i++) {
        float c[8];
#pragma unroll
        for (int p = 0; p < 4; p++) {
            float2 v = unpack2(acc2[i][p]);
            c[2 * p]     = v.x + bb[2 * p];
            c[2 * p + 1] = v.y + bb[2 * p + 1];
        }
        const size_t row = (size_t)(m0 + ty * 8 + i) * N + n0 + tx * 8;
        *reinterpret_cast<float4*>(&C[row])     = make_float4(c[0], c[1], c[2], c[3]);
        *reinterpret_cast<float4*>(&C[row + 4]) = make_float4(c[4], c[5], c[6], c[7]);
    }
}

// ---------------------------------------------------------------------------
__device__ __forceinline__ float sigf(float x) { return 1.0f / (1.0f + __expf(-x)); }

__device__ __forceinline__ void grid_barrier(unsigned& lsense)
{
    __threadfence();
    __syncthreads();
    if (threadIdx.x == 0) {
        const unsigned target = lsense ^ 1u;
        if (atomicAdd(&g_count, 1u) == (unsigned)(NCTA - 1)) {
            g_count = 0;
            __threadfence();
            *((volatile unsigned*)&g_sense) = target;
        } else {
            while (*((volatile unsigned*)&g_sense) != target) { }
        }
    }
    __syncthreads();
    lsense ^= 1u;
}

// ---------------------------------------------------------------------------
// Persistent recurrence: 128 CTAs = 32 j-blocks x 4 b-blocks; CTA owns
// 16 hidden columns x 32 batches. Weights (160 KB) live in SMEM.
// Thread = (bloc = tid&31, jh = (tid>>5)&1, kg = tid>>6). Each thread
// computes 8 j (4 f32x2 pairs) x 5 gates over a K-quarter (128 k), with
// chunked double-buffered state loads. 4-way k reduction via SMEM.
// L2 state traffic: 16 MB/step (4x less than the 1D-j partition).
// ---------------------------------------------------------------------------

#define LOAD_CHUNK(BUF, CH) do {                                          \
    const int kb_ = kg * 128 + (CH) * 16;                                 \
    _Pragma("unroll")                                                     \
    for (int i_ = 0; i_ < 16; i_++)                                       \
        BUF[i_] = __ldcg(st + (size_t)(kb_ + i_) * 128 + bglob);          \
} while (0)

#define COMPUTE_CHUNK(BUF, CH) do {                                      \
    _Pragma("unroll")                                                     \
    for (int t_ = 0; t_ < 8; t_++) {                                      \
        const int kp_ = kg * 64 + (CH) * 8 + t_;                          \
        const unsigned long long hh0 = pack2(BUF[2 * t_].x);              \
        const unsigned long long cc0 = pack2(BUF[2 * t_].y);              \
        const unsigned long long hh1 = pack2(BUF[2 * t_ + 1].x);          \
        const unsigned long long cc1 = pack2(BUF[2 * t_ + 1].y);          \
        _Pragma("unroll")                                                 \
        for (int jp_ = 0; jp_ < 4; jp_++) {                               \
            _Pragma("unroll")                                             \
            for (int g_ = 0; g_ < 4; g_++) {                              \
                ulonglong2 w = Us2[((jh * 4 + jp_) * 4 + g_) * 256 + kp_];\
                fma2(acc[jp_ * 5 + g_], hh0, w.x);                        \
                fma2(acc[jp_ * 5 + g_], hh1, w.y);                        \
            }                                                             \
        }                                                                 \
        _Pragma("unroll")                                                 \
        for (int jp_ = 0; jp_ < 4; jp_++) {                               \
            ulonglong2 w = Wd2[(jh * 4 + jp_) * 256 + kp_];               \
            fma2(acc[jp_ * 5 + 4], cc0, w.x);                             \
            fma2(acc[jp_ * 5 + 4], cc1, w.y);                             \
        }                                                                 \
    }                                                                     \
} while (0)

__global__ void __launch_bounds__(256, 1)
tlstm_recur(const float* __restrict__ U_all, const float* __restrict__ b_u,
            const float* __restrict__ W_d,  const float* __restrict__ b_d,
            const float* __restrict__ td,
            float* __restrict__ hs_out, float* __restrict__ cs_out)
{
    extern __shared__ unsigned long long smem_u[];
    ulonglong2* Us2 = (ulonglong2*)smem_u;                    // 8192 ull2 = 128 KB
    ulonglong2* Wd2 = (ulonglong2*)(smem_u + 16384);          // 2048 ull2 = 32 KB
    float* red  = (float*)(smem_u + 20480);                   // 10240 floats = 40 KB
    float* bu_s = red + 10240;                                // [g*16 + jl] : 64
    float* bd_s = bu_s + 64;                                  // [jl] : 16

    const int tid  = threadIdx.x;
    const int cid  = blockIdx.x;
    const int jb   = cid >> 2;          // j-block (0..31): j = jb*16 ..
    const int bb   = cid & 3;           // b-block (0..3):  b = bb*32 ..

    const int bloc = tid & 31;
    const int jh   = (tid >> 5) & 1;
    const int kg   = tid >> 6;
    const int bglob = bb * 32 + bloc;

    // ---- one-time staging: packed weight pairs into SMEM ----
    {
        float* UsF = (float*)Us2;
        for (int i = tid; i < 32768; i += 256) {
            const int lane = i & 1;
            const int h    = (i >> 1) & 1;
            const int kp   = (i >> 2) & 255;
            const int g    = (i >> 10) & 3;
            const int jp   = (i >> 12) & 3;
            const int jhh  = (i >> 14) & 1;
            const int k    = kp * 2 + h;
            const int j    = jb * 16 + jhh * 8 + jp * 2 + lane;
            UsF[i] = U_all[(size_t)k * 2048 + g * 512 + j];
        }
        float* WdF = (float*)Wd2;
        for (int i = tid; i < 8192; i += 256) {
            const int lane = i & 1;
            const int h    = (i >> 1) & 1;
            const int kp   = (i >> 2) & 255;
            const int jp   = (i >> 10) & 3;
            const int jhh  = (i >> 12) & 1;
            const int j    = jb * 16 + jhh * 8 + jp * 2 + lane;
            WdF[i] = W_d[(size_t)(kp * 2 + h) * 512 + j];
        }
        if (tid < 64) bu_s[tid] = b_u[(tid >> 4) * 512 + jb * 16 + (tid & 15)];
        if (tid < 16) bd_s[tid] = b_d[jb * 16 + tid];
    }

    // zero ping buffer 0 (disjoint slice per CTA; 128 CTAs cover 65536 float2)
    {
        float2* stz = reinterpret_cast<float2*>(g_state);
        for (int i = tid; i < 512; i += 256)
            stz[cid * 512 + i] = make_float2(0.f, 0.f);
    }

    unsigned lsense = *((volatile unsigned*)&g_sense);
    grid_barrier(lsense);

    // final-phase mapping (independent of dot-loop mapping)
    const int bo    = tid >> 3;             // 0..31
    const int jq    = tid & 7;              // j-pair within 16
    const int jh2   = jq >> 2;
    const int jp2   = jq & 3;
    const int jglob = jb * 16 + jq * 2;
    const int bg2   = bb * 32 + bo;

    for (int s = 0; s < Sn; s++) {
        if (s) grid_barrier(lsense);

        const float2* st = reinterpret_cast<const float2*>(g_state) + (size_t)(s & 1) * (Hn * Bn);
        float2*      stn = reinterpret_cast<float2*>(g_state) + (size_t)((s & 1) ^ 1) * (Hn * Bn);

        // ---- prefetch final-phase operands (consumed after the dot loop) ----
        const float* wxb = g_wx + ((size_t)bg2 * Sn + s) * 2048 + jglob;
        const float2 wxF = *reinterpret_cast<const float2*>(wxb + 0 * 512);
        const float2 wxI = *reinterpret_cast<const float2*>(wxb + 1 * 512);
        const float2 wxO = *reinterpret_cast<const float2*>(wxb + 2 * 512);
        const float2 wxG = *reinterpret_cast<const float2*>(wxb + 3 * 512);
        const float  co0 = __ldcg(st + (size_t)jglob * 128 + bg2).y;
        const float  co1 = __ldcg(st + (size_t)(jglob + 1) * 128 + bg2).y;
        const float  tdv = __ldg(td + (size_t)bg2 * Sn + s);

        // ---- dot products over this thread's K-quarter (chunked, MLP=16) ----
        unsigned long long acc[20];
#pragma unroll
        for (int i = 0; i < 20; i++) acc[i] = 0ull;

        float2 bufA[16], bufB[16];
        LOAD_CHUNK(bufA, 0);

#pragma unroll 1
        for (int ch = 0; ch < 8; ch += 2) {
            LOAD_CHUNK(bufB, ch + 1);
            COMPUTE_CHUNK(bufA, ch);
            if (ch + 2 < 8) LOAD_CHUNK(bufA, ch + 2);
            COMPUTE_CHUNK(bufB, ch + 1);
        }

        // ---- write partials: red[(kg*32+bloc)*2 + jh][40] ----
        {
            float2* pr = reinterpret_cast<float2*>(
                red + (size_t)(((kg * 32 + bloc) * 2 + jh) * 40));
#pragma unroll
            for (int i = 0; i < 20; i++) pr[i] = unpack2(acc[i]);
        }
        __syncthreads();

        // ---- final phase: sum 4 k-quarters, apply gates, write outputs ----
        {
            float2 G[5];
#pragma unroll
            for (int g = 0; g < 5; g++) {
                float2 sum = make_float2(0.f, 0.f);
#pragma unroll
                for (int q = 0; q < 4; q++) {
                    float2 v = *reinterpret_cast<const float2*>(
                        red + (size_t)(((q * 32 + bo) * 2 + jh2) * 40 + (jp2 * 5 + g) * 2));
                    sum.x += v.x; sum.y += v.y;
                }
                G[g] = sum;
            }

            const int jl = jq * 2;
            // lane 0
            const float cst0  = sigf(G[4].x + bd_s[jl]);
            const float cadj0 = co0 - cst0 + cst0 * tdv;
            const float ff0   = sigf(wxF.x + G[0].x + bu_s[jl]);
            const float ii0   = sigf(wxI.x + G[1].x + bu_s[16 + jl]);
            const float oo0   = sigf(wxO.x + G[2].x + bu_s[32 + jl]);
            const float gg0   = tanhf(wxG.x + G[3].x + bu_s[48 + jl]);
            const float cn0   = ff0 * cadj0 + ii0 * gg0;
            const float hn0   = oo0 * tanhf(cn0);
            // lane 1
            const float cst1  = sigf(G[4].y + bd_s[jl + 1]);
            const float cadj1 = co1 - cst1 + cst1 * tdv;
            const float ff1   = sigf(wxF.y + G[0].y + bu_s[jl + 1]);
            const float ii1   = sigf(wxI.y + G[1].y + bu_s[16 + jl + 1]);
            const float oo1   = sigf(wxO.y + G[2].y + bu_s[32 + jl + 1]);
            const float gg1   = tanhf(wxG.y + G[3].y + bu_s[48 + jl + 1]);
            const float cn1   = ff1 * cadj1 + ii1 * gg1;
            const float hn1   = oo1 * tanhf(cn1);

            stn[(size_t)jglob * 128 + bg2]       = make_float2(hn0, cn0);
            stn[(size_t)(jglob + 1) * 128 + bg2] = make_float2(hn1, cn1);

            const size_t ob = ((size_t)bg2 * Sn + s) * Hn + jglob;
            *reinterpret_cast<float2*>(hs_out + ob) = make_float2(hn0, hn1);
            *reinterpret_cast<float2*>(cs_out + ob) = make_float2(cn0, cn1);
        }
    }
}

// ---------------------------------------------------------------------------
// Launch
// ---------------------------------------------------------------------------
extern "C" void kernel_launch(void* const* d_in, const int* in_sizes, int n_in,
                              void* d_out, int out_size)
{
    const float* inputs     = (const float*)d_in[0];
    const float* time_diffs = (const float*)d_in[1];
    // d_in[2] = seq_lens (unused by reference)
    const float* W_all      = (const float*)d_in[3];
    const float* b_all      = (const float*)d_in[4];
    const float* U_all      = (const float*)d_in[5];
    const float* b_u        = (const float*)d_in[6];
    const float* W_d        = (const float*)d_in[7];
    const float* b_d        = (const float*)d_in[8];
    const float* W_out      = (const float*)d_in[9];
    const float* b_out      = (const float*)d_in[10];

    float* out = (float*)d_out;                        // [B,S,O]
    float* hs  = out + (size_t)Bn * Sn * On;           // [B,S,H]
    float* cs  = hs  + (size_t)Bn * Sn * Hn;           // [B,S,H]

    const int M = Bn * Sn;  // 65536

    // GEMM1: Wx = inputs @ W_all + b_all  -> g_wx
    {
        dim3 grid((4 * Hn) / 128, M / 128);
        sgemm_bias<<<grid, 256>>>(inputs, W_all, b_all, nullptr, M, 4 * Hn, Dn);
    }

    // Recurrence: persistent grid, grid-wide barrier per step
    {
        const int shmem = 20480 * 8 + 10240 * 4 + 80 * 4;   // 205120 B
        cudaFuncSetAttribute(tlstm_recur,
                             cudaFuncAttributeMaxDynamicSharedMemorySize, shmem);
        tlstm_recur<<<NCTA, 256, shmem>>>(U_all, b_u, W_d, b_d, time_diffs, hs, cs);
    }

    // GEMM2: outputs = hs @ W_out + b_out
    {
        dim3 grid(On / 128, M / 128);
        sgemm_bias<<<grid, 256>>>(hs, W_out, b_out, out, M, On, Hn);
    }
}

// round 14
// speedup vs baseline: 1.1219x; 1.0010x over previous
#include <cuda_runtime.h>
#include <cstddef>

#define Bn 128
#define Sn 512
#define Dn 256
#define Hn 512
#define On 256
#define NCTA 128

// ---------------------------------------------------------------------------
// Device scratch (static __device__ globals — the sanctioned no-alloc scratch)
// ---------------------------------------------------------------------------
__device__ __align__(16) float g_wx[(size_t)Bn * Sn * 4 * Hn];   // [b*S+s][4H]
__device__ __align__(16) float g_state[2 * Hn * Bn * 2];         // ping-pong, float2(h,c), k-major
__device__ unsigned g_count = 0;
__device__ unsigned g_sense = 0;

// ---------------------------------------------------------------------------
// f32x2 packed helpers (sm_103a)
// ---------------------------------------------------------------------------
__device__ __forceinline__ unsigned long long pack2(float v) {
    unsigned long long r;
    asm("mov.b64 %0, {%1, %1};" : "=l"(r) : "f"(v));
    return r;
}
__device__ __forceinline__ void fma2(unsigned long long& d,
                                     unsigned long long a, unsigned long long b) {
    asm("fma.rn.f32x2 %0, %1, %2, %0;" : "+l"(d) : "l"(a), "l"(b));
}
__device__ __forceinline__ float2 unpack2(unsigned long long v) {
    float2 r;
    asm("mov.b64 {%0, %1}, %2;" : "=f"(r.x), "=f"(r.y) : "l"(v));
    return r;
}

// ---------------------------------------------------------------------------
// SGEMM with bias (f32x2 accumulators): C[M,N] = A[M,K] @ B[K,N] + bias[N]
// BM=BN=128, BK=16, 256 threads, 8x8 per thread as 8 rows x 4 f32x2 pairs.
// ---------------------------------------------------------------------------
__global__ void __launch_bounds__(256)
sgemm_bias(const float* __restrict__ A, const float* __restrict__ Bm,
           const float* __restrict__ bias, float* __restrict__ C,
           int M, int N, int K)
{
    if (C == nullptr) C = g_wx;

    __shared__ float As[16][132];
    __shared__ float Bs[16][132];

    const int tid = threadIdx.x;
    const int tx = tid & 15;
    const int ty = tid >> 4;
    const int m0 = blockIdx.y * 128;
    const int n0 = blockIdx.x * 128;

    unsigned long long acc2[8][4];
#pragma unroll
    for (int i = 0; i < 8; i++)
#pragma unroll
        for (int p = 0; p < 4; p++) acc2[i][p] = 0ull;

    const int ar = tid >> 1;
    const int ah = tid & 1;
    const float* Abase = A + (size_t)(m0 + ar) * K + ah * 8;
    const int bk = tid >> 5;
    const int bc = (tid & 31) * 4;

    for (int k0 = 0; k0 < K; k0 += 16) {
        float4 a0 = *reinterpret_cast<const float4*>(Abase + k0);
        float4 a1 = *reinterpret_cast<const float4*>(Abase + k0 + 4);
        As[ah * 8 + 0][ar] = a0.x; As[ah * 8 + 1][ar] = a0.y;
        As[ah * 8 + 2][ar] = a0.z; As[ah * 8 + 3][ar] = a0.w;
        As[ah * 8 + 4][ar] = a1.x; As[ah * 8 + 5][ar] = a1.y;
        As[ah * 8 + 6][ar] = a1.z; As[ah * 8 + 7][ar] = a1.w;
#pragma unroll
        for (int p = 0; p < 16; p += 8) {
            float4 bv = *reinterpret_cast<const float4*>(
                Bm + (size_t)(k0 + bk + p) * N + n0 + bc);
            *reinterpret_cast<float4*>(&Bs[bk + p][bc]) = bv;
        }
        __syncthreads();

#pragma unroll
        for (int k = 0; k < 16; k++) {
            float ra[8];
            *reinterpret_cast<float4*>(ra)     = *reinterpret_cast<const float4*>(&As[k][ty * 8]);
            *reinterpret_cast<float4*>(ra + 4) = *reinterpret_cast<const float4*>(&As[k][ty * 8 + 4]);
            ulonglong2 u0 = *reinterpret_cast<const ulonglong2*>(&Bs[k][tx * 8]);
            ulonglong2 u1 = *reinterpret_cast<const ulonglong2*>(&Bs[k][tx * 8 + 4]);
#pragma unroll
            for (int i = 0; i < 8; i++) {
                const unsigned long long rah = pack2(ra[i]);
                fma2(acc2[i][0], rah, u0.x);
                fma2(acc2[i][1], rah, u0.y);
                fma2(acc2[i][2], rah, u1.x);
                fma2(acc2[i][3], rah, u1.y);
            }
        }
        __syncthreads();
    }

    float bb[8];
#pragma unroll
    for (int j = 0; j < 8; j++) bb[j] = bias[n0 + tx * 8 + j];

#pragma unroll
    for (int i = 0; i < 8; i++) {
        float c[8];
#pragma unroll
        for (int p = 0; p < 4; p++) {
            float2 v = unpack2(acc2[i][p]);
            c[2 * p]     = v.x + bb[2 * p];
            c[2 * p + 1] = v.y + bb[2 * p + 1];
        }
        const size_t row = (size_t)(m0 + ty * 8 + i) * N + n0 + tx * 8;
        *reinterpret_cast<float4*>(&C[row])     = make_float4(c[0], c[1], c[2], c[3]);
        *reinterpret_cast<float4*>(&C[row + 4]) = make_float4(c[4], c[5], c[6], c[7]);
    }
}

// ---------------------------------------------------------------------------
__device__ __forceinline__ float sigf(float x) { return 1.0f / (1.0f + __expf(-x)); }

__device__ __forceinline__ void grid_barrier(unsigned& lsense)
{
    __threadfence();
    __syncthreads();
    if (threadIdx.x == 0) {
        const unsigned target = lsense ^ 1u;
        if (atomicAdd(&g_count, 1u) == (unsigned)(NCTA - 1)) {
            g_count = 0;
            __threadfence();
            *((volatile unsigned*)&g_sense) = target;
        } else {
            while (*((volatile unsigned*)&g_sense) != target) { }
        }
    }
    __syncthreads();
    lsense ^= 1u;
}

// ---------------------------------------------------------------------------
// Persistent recurrence: 128 CTAs = 32 j-blocks x 4 b-blocks; CTA owns
// 16 hidden columns x 32 batches. Weights (160 KB) live in SMEM.
// Thread = (bloc = tid&31, jh = (tid>>5)&1, kg = tid>>6). Each thread
// computes 8 j (4 f32x2 pairs) x 5 gates over a K-quarter (128 k), with
// chunked double-buffered state loads. 4-way k reduction via SMEM.
// L2 state traffic: 16 MB/step (4x less than the 1D-j partition).
// ---------------------------------------------------------------------------

#define LOAD_CHUNK(BUF, CH) do {                                          \
    const int kb_ = kg * 128 + (CH) * 16;                                 \
    _Pragma("unroll")                                                     \
    for (int i_ = 0; i_ < 16; i_++)                                       \
        BUF[i_] = __ldcg(st + (size_t)(kb_ + i_) * 128 + bglob);          \
} while (0)

#define COMPUTE_CHUNK(BUF, CH) do {                                      \
    _Pragma("unroll")                                                     \
    for (int t_ = 0; t_ < 8; t_++) {                                      \
        const int kp_ = kg * 64 + (CH) * 8 + t_;                          \
        const unsigned long long hh0 = pack2(BUF[2 * t_].x);              \
        const unsigned long long cc0 = pack2(BUF[2 * t_].y);              \
        const unsigned long long hh1 = pack2(BUF[2 * t_ + 1].x);          \
        const unsigned long long cc1 = pack2(BUF[2 * t_ + 1].y);          \
        _Pragma("unroll")                                                 \
        for (int jp_ = 0; jp_ < 4; jp_++) {                               \
            _Pragma("unroll")                                             \
            for (int g_ = 0; g_ < 4; g_++) {                              \
                ulonglong2 w = Us2[((jh * 4 + jp_) * 4 + g_) * 256 + kp_];\
                fma2(acc[jp_ * 5 + g_], hh0, w.x);                        \
                fma2(acc[jp_ * 5 + g_], hh1, w.y);                        \
            }                                                             \
        }                                                                 \
        _Pragma("unroll")                                                 \
        for (int jp_ = 0; jp_ < 4; jp_++) {                               \
            ulonglong2 w = Wd2[(jh * 4 + jp_) * 256 + kp_];               \
            fma2(acc[jp_ * 5 + 4], cc0, w.x);                             \
            fma2(acc[jp_ * 5 + 4], cc1, w.y);                             \
        }                                                                 \
    }                                                                     \
} while (0)

__global__ void __launch_bounds__(256, 1)
tlstm_recur(const float* __restrict__ U_all, const float* __restrict__ b_u,
            const float* __restrict__ W_d,  const float* __restrict__ b_d,
            const float* __restrict__ td,
            float* __restrict__ hs_out, float* __restrict__ cs_out)
{
    extern __shared__ unsigned long long smem_u[];
    ulonglong2* Us2 = (ulonglong2*)smem_u;                    // 8192 ull2 = 128 KB
    ulonglong2* Wd2 = (ulonglong2*)(smem_u + 16384);          // 2048 ull2 = 32 KB
    float* red  = (float*)(smem_u + 20480);                   // 10240 floats = 40 KB
    float* bu_s = red + 10240;                                // [g*16 + jl] : 64
    float* bd_s = bu_s + 64;                                  // [jl] : 16

    const int tid  = threadIdx.x;
    const int cid  = blockIdx.x;
    const int jb   = cid >> 2;          // j-block (0..31): j = jb*16 ..
    const int bb   = cid & 3;           // b-block (0..3):  b = bb*32 ..

    const int bloc = tid & 31;
    const int jh   = (tid >> 5) & 1;
    const int kg   = tid >> 6;
    const int bglob = bb * 32 + bloc;

    // ---- one-time staging: packed weight pairs into SMEM ----
    {
        float* UsF = (float*)Us2;
        for (int i = tid; i < 32768; i += 256) {
            const int lane = i & 1;
            const int h    = (i >> 1) & 1;
            const int kp   = (i >> 2) & 255;
            const int g    = (i >> 10) & 3;
            const int jp   = (i >> 12) & 3;
            const int jhh  = (i >> 14) & 1;
            const int k    = kp * 2 + h;
            const int j    = jb * 16 + jhh * 8 + jp * 2 + lane;
            UsF[i] = U_all[(size_t)k * 2048 + g * 512 + j];
        }
        float* WdF = (float*)Wd2;
        for (int i = tid; i < 8192; i += 256) {
            const int lane = i & 1;
            const int h    = (i >> 1) & 1;
            const int kp   = (i >> 2) & 255;
            const int jp   = (i >> 10) & 3;
            const int jhh  = (i >> 12) & 1;
            const int j    = jb * 16 + jhh * 8 + jp * 2 + lane;
            WdF[i] = W_d[(size_t)(kp * 2 + h) * 512 + j];
        }
        if (tid < 64) bu_s[tid] = b_u[(tid >> 4) * 512 + jb * 16 + (tid & 15)];
        if (tid < 16) bd_s[tid] = b_d[jb * 16 + tid];
    }

    // zero ping buffer 0 (disjoint slice per CTA; 128 CTAs cover 65536 float2)
    {
        float2* stz = reinterpret_cast<float2*>(g_state);
        for (int i = tid; i < 512; i += 256)
            stz[cid * 512 + i] = make_float2(0.f, 0.f);
    }

    unsigned lsense = *((volatile unsigned*)&g_sense);
    grid_barrier(lsense);

    // final-phase mapping (independent of dot-loop mapping)
    const int bo    = tid >> 3;             // 0..31
    const int jq    = tid & 7;              // j-pair within 16
    const int jh2   = jq >> 2;
    const int jp2   = jq & 3;
    const int jglob = jb * 16 + jq * 2;
    const int bg2   = bb * 32 + bo;

    for (int s = 0; s < Sn; s++) {
        if (s) grid_barrier(lsense);

        const float2* st = reinterpret_cast<const float2*>(g_state) + (size_t)(s & 1) * (Hn * Bn);
        float2*      stn = reinterpret_cast<float2*>(g_state) + (size_t)((s & 1) ^ 1) * (Hn * Bn);

        // ---- prefetch final-phase operands (consumed after the dot loop) ----
        const float* wxb = g_wx + ((size_t)bg2 * Sn + s) * 2048 + jglob;
        const float2 wxF = *reinterpret_cast<const float2*>(wxb + 0 * 512);
        const float2 wxI = *reinterpret_cast<const float2*>(wxb + 1 * 512);
        const float2 wxO = *reinterpret_cast<const float2*>(wxb + 2 * 512);
        const float2 wxG = *reinterpret_cast<const float2*>(wxb + 3 * 512);
        const float  co0 = __ldcg(st + (size_t)jglob * 128 + bg2).y;
        const float  co1 = __ldcg(st + (size_t)(jglob + 1) * 128 + bg2).y;
        const float  tdv = __ldg(td + (size_t)bg2 * Sn + s);

        // ---- dot products over this thread's K-quarter (chunked, MLP=16) ----
        unsigned long long acc[20];
#pragma unroll
        for (int i = 0; i < 20; i++) acc[i] = 0ull;

        float2 bufA[16], bufB[16];
        LOAD_CHUNK(bufA, 0);

#pragma unroll 1
        for (int ch = 0; ch < 8; ch += 2) {
            LOAD_CHUNK(bufB, ch + 1);
            COMPUTE_CHUNK(bufA, ch);
            if (ch + 2 < 8) LOAD_CHUNK(bufA, ch + 2);
            COMPUTE_CHUNK(bufB, ch + 1);
        }

        // ---- write partials: red[(kg*32+bloc)*2 + jh][40] ----
        {
            float2* pr = reinterpret_cast<float2*>(
                red + (size_t)(((kg * 32 + bloc) * 2 + jh) * 40));
#pragma unroll
            for (int i = 0; i < 20; i++) pr[i] = unpack2(acc[i]);
        }
        __syncthreads();

        // ---- final phase: sum 4 k-quarters, apply gates, write outputs ----
        {
            float2 G[5];
#pragma unroll
            for (int g = 0; g < 5; g++) {
                float2 sum = make_float2(0.f, 0.f);
#pragma unroll
                for (int q = 0; q < 4; q++) {
                    float2 v = *reinterpret_cast<const float2*>(
                        red + (size_t)(((q * 32 + bo) * 2 + jh2) * 40 + (jp2 * 5 + g) * 2));
                    sum.x += v.x; sum.y += v.y;
                }
                G[g] = sum;
            }

            const int jl = jq * 2;
            // lane 0
            const float cst0  = sigf(G[4].x + bd_s[jl]);
            const float cadj0 = co0 - cst0 + cst0 * tdv;
            const float ff0   = sigf(wxF.x + G[0].x + bu_s[jl]);
            const float ii0   = sigf(wxI.x + G[1].x + bu_s[16 + jl]);
            const float oo0   = sigf(wxO.x + G[2].x + bu_s[32 + jl]);
            const float gg0   = tanhf(wxG.x + G[3].x + bu_s[48 + jl]);
            const float cn0   = ff0 * cadj0 + ii0 * gg0;
            const float hn0   = oo0 * tanhf(cn0);
            // lane 1
            const float cst1  = sigf(G[4].y + bd_s[jl + 1]);
            const float cadj1 = co1 - cst1 + cst1 * tdv;
            const float ff1   = sigf(wxF.y + G[0].y + bu_s[jl + 1]);
            const float ii1   = sigf(wxI.y + G[1].y + bu_s[16 + jl + 1]);
            const float oo1   = sigf(wxO.y + G[2].y + bu_s[32 + jl + 1]);
            const float gg1   = tanhf(wxG.y + G[3].y + bu_s[48 + jl + 1]);
            const float cn1   = ff1 * cadj1 + ii1 * gg1;
            const float hn1   = oo1 * tanhf(cn1);

            stn[(size_t)jglob * 128 + bg2]       = make_float2(hn0, cn0);
            stn[(size_t)(jglob + 1) * 128 + bg2] = make_float2(hn1, cn1);

            const size_t ob = ((size_t)bg2 * Sn + s) * Hn + jglob;
            *reinterpret_cast<float2*>(hs_out + ob) = make_float2(hn0, hn1);
            *reinterpret_cast<float2*>(cs_out + ob) = make_float2(cn0, cn1);
        }
    }
}

// ---------------------------------------------------------------------------
// Launch
// ---------------------------------------------------------------------------
extern "C" void kernel_launch(void* const* d_in, const int* in_sizes, int n_in,
                              void* d_out, int out_size)
{
    const float* inputs     = (const float*)d_in[0];
    const float* time_diffs = (const float*)d_in[1];
    // d_in[2] = seq_lens (unused by reference)
    const float* W_all      = (const float*)d_in[3];
    const float* b_all      = (const float*)d_in[4];
    const float* U_all      = (const float*)d_in[5];
    const float* b_u        = (const float*)d_in[6];
    const float* W_d        = (const float*)d_in[7];
    const float* b_d        = (const float*)d_in[8];
    const float* W_out      = (const float*)d_in[9];
    const float* b_out      = (const float*)d_in[10];

    float* out = (float*)d_out;                        // [B,S,O]
    float* hs  = out + (size_t)Bn * Sn * On;           // [B,S,H]
    float* cs  = hs  + (size_t)Bn * Sn * Hn;           // [B,S,H]

    const int M = Bn * Sn;  // 65536

    // GEMM1: Wx = inputs @ W_all + b_all  -> g_wx
    {
        dim3 grid((4 * Hn) / 128, M / 128);
        sgemm_bias<<<grid, 256>>>(inputs, W_all, b_all, nullptr, M, 4 * Hn, Dn);
    }

    // Recurrence: persistent grid, grid-wide barrier per step
    {
        const int shmem = 20480 * 8 + 10240 * 4 + 80 * 4;   // 205120 B
        cudaFuncSetAttribute(tlstm_recur,
                             cudaFuncAttributeMaxDynamicSharedMemorySize, shmem);
        tlstm_recur<<<NCTA, 256, shmem>>>(U_all, b_u, W_d, b_d, time_diffs, hs, cs);
    }

    // GEMM2: outputs = hs @ W_out + b_out
    {
        dim3 grid(On / 128, M / 128);
        sgemm_bias<<<grid, 256>>>(hs, W_out, b_out, out, M, On, Hn);
    }
}